// round 3
// baseline (speedup 1.0000x reference)
#include <cuda_runtime.h>
#include <cuda_bf16.h>
#include <cstddef>

// Shapes: B=64, C=32, H=8, Wd=8 -> P=2048 positions, I=16, O=32, D=32
#define B_  64
#define P_  2048
#define I_  16
#define O_  32
#define D_  32
#define OD_ 1024                 // O_*D_
#define EPS 1e-6f

// ---------------- scratch (device globals; no allocation allowed) ----------
__device__ float g_uhat[(size_t)B_ * P_ * OD_];   // 512 MB  [b][p][o][d]
__device__ float g_b[(size_t)B_ * P_ * O_];       // 16 MB   [b][p][o]
__device__ float g_s1[B_ * OD_];                  // transposed [b][d*32+o]
__device__ float g_s2[B_ * OD_];
__device__ float g_s3[B_ * OD_];
__device__ float g_v [B_ * OD_];                  // transposed [b][d*32+o]

// ---------------- zero the atomic accumulators every launch -----------------
__global__ void k_zero() {
    int i = blockIdx.x * blockDim.x + threadIdx.x;
    if (i < B_ * OD_) { g_s1[i] = 0.f; g_s2[i] = 0.f; g_s3[i] = 0.f; }
}

// ---------------- K1: u_hat[b,p,o,d] = sum_i x[b,p,i] * W[p,o,i,d] ---------
// One block per p. W slice for this thread's (o, d0..d0+3) cached in registers
// (64 floats); loop over all 64 b with x broadcast from smem.
__global__ void __launch_bounds__(256) k_uhat(const float* __restrict__ x,
                                              const float* __restrict__ Wg) {
    const int p  = blockIdx.x;
    const int t  = threadIdx.x;
    const int o  = t >> 3;            // 0..31
    const int d0 = (t & 7) * 4;       // 0,4,...,28

    __shared__ float sx[B_ * I_];     // 4 KB: x[b][i] for this p
    for (int k = t; k < B_ * I_; k += 256) {
        int b = k >> 4, i = k & 15;
        sx[k] = x[(size_t)b * (P_ * I_) + (size_t)p * I_ + i];
    }

    // W[p, o, i, d0..d0+3] into registers
    float4 w[I_];
    const float4* wp = reinterpret_cast<const float4*>(
        Wg + (size_t)p * (O_ * I_ * D_) + (size_t)o * (I_ * D_) + d0);
#pragma unroll
    for (int i = 0; i < I_; i++) w[i] = wp[i * (D_ / 4)];

    __syncthreads();

    float4* outp = reinterpret_cast<float4*>(g_uhat + (size_t)p * OD_ + t * 4);
    const size_t bstride4 = (size_t)P_ * OD_ / 4;   // float4 stride between b
#pragma unroll 2
    for (int b = 0; b < B_; b++) {
        const float* xb = sx + b * I_;
        float4 a = make_float4(0.f, 0.f, 0.f, 0.f);
#pragma unroll
        for (int i = 0; i < I_; i++) {
            float xv = xb[i];
            a.x = fmaf(xv, w[i].x, a.x);
            a.y = fmaf(xv, w[i].y, a.y);
            a.z = fmaf(xv, w[i].z, a.z);
            a.w = fmaf(xv, w[i].w, a.w);
        }
        outp[(size_t)b * bstride4] = a;
    }
}

// ---------------- s1 = sum_p u_hat  (uniform c applied later as 1/32) ------
// grid (16 p-slices, 64 b), 256 threads; writes transposed [d*32+o] layout.
__global__ void __launch_bounds__(256) k_s0() {
    const int b     = blockIdx.y;
    const int pbase = blockIdx.x * 128;
    const int t     = threadIdx.x;

    const float4* up = reinterpret_cast<const float4*>(
        g_uhat + ((size_t)b * P_ + pbase) * OD_) + t;
    float4 a = make_float4(0.f, 0.f, 0.f, 0.f);
    for (int p = 0; p < 128; p++) {
        float4 u = up[(size_t)p * (OD_ / 4)];
        a.x += u.x; a.y += u.y; a.z += u.z; a.w += u.w;
    }
    const int o = t >> 3, d0 = (t & 7) * 4;
    float* s = g_s1 + b * OD_;
    atomicAdd(&s[(d0 + 0) * O_ + o], a.x);
    atomicAdd(&s[(d0 + 1) * O_ + o], a.y);
    atomicAdd(&s[(d0 + 2) * O_ + o], a.z);
    atomicAdd(&s[(d0 + 3) * O_ + o], a.w);
}

// ---------------- squash: v = |s|^2/(1+|s|^2) * s/(|s|+eps) ----------------
// grid 64 (b), block 1024: warp = o, lane = d. Reads transposed layout.
// dst == nullptr -> write g_v (transposed); else write dst in (b,o,d) layout.
__global__ void k_squash(int src, float scale, float* __restrict__ dst) {
    const int b = blockIdx.x;
    const int o = threadIdx.x >> 5;
    const int d = threadIdx.x & 31;
    const float* sin = (src == 1) ? g_s1 : (src == 2) ? g_s2 : g_s3;
    float s = sin[b * OD_ + d * O_ + o] * scale;
    float sq = s * s;
#pragma unroll
    for (int off = 16; off; off >>= 1)
        sq += __shfl_xor_sync(0xffffffffu, sq, off);
    float f = sq / ((1.f + sq) * (sqrtf(sq) + EPS));
    float v = s * f;
    if (dst) dst[b * OD_ + o * D_ + d] = v;
    else     g_v[b * OD_ + d * O_ + o] = v;
}

// ---------------- fused routing pass ---------------------------------------
// ONE read of u_hat does:  b_new = b_prev + u.v ; c = softmax_o(b_new);
// s_next += c * u   (per-warp register partials -> smem -> atomics).
// grid (32 p-chunks of 64, 64 b), 256 threads = 8 warps, 8 p's per warp.
// lane = o.
__global__ void __launch_bounds__(256) k_route(int pass) {
    const int b     = blockIdx.y;
    const int pbase = blockIdx.x * 64;
    const int w     = threadIdx.x >> 5;
    const int lane  = threadIdx.x & 31;

    const float* bprev = (pass == 2) ? g_b : nullptr;
    float*       sout  = (pass == 1) ? g_s2 : g_s3;

    __shared__ float sacc[8][OD_];     // 32 KB, per-warp partials (transposed)

    // v row for this lane's o, from transposed g_v: coalesced across lanes
    float v[D_];
    const float* vb = g_v + b * OD_;
#pragma unroll
    for (int d = 0; d < D_; d++) v[d] = vb[d * O_ + lane];

    float sreg[D_];
#pragma unroll
    for (int d = 0; d < D_; d++) sreg[d] = 0.f;

    for (int j = 0; j < 8; j++) {
        const int p = pbase + w * 8 + j;
        const float4* up = reinterpret_cast<const float4*>(
            g_uhat + ((size_t)b * P_ + p) * OD_ + lane * D_);
        float u[D_];
#pragma unroll
        for (int q = 0; q < 8; q++) {
            float4 t4 = up[q];
            u[q * 4 + 0] = t4.x; u[q * 4 + 1] = t4.y;
            u[q * 4 + 2] = t4.z; u[q * 4 + 3] = t4.w;
        }
        float dot = 0.f;
#pragma unroll
        for (int d = 0; d < D_; d++) dot = fmaf(u[d], v[d], dot);

        const size_t bidx = ((size_t)b * P_ + p) * O_ + lane;
        float bn = dot;
        if (bprev) bn += bprev[bidx];
        g_b[bidx] = bn;

        // softmax over o (= warp lanes), max-subtracted
        float m = bn;
#pragma unroll
        for (int off = 16; off; off >>= 1)
            m = fmaxf(m, __shfl_xor_sync(0xffffffffu, m, off));
        float e = __expf(bn - m);
        float ssum = e;
#pragma unroll
        for (int off = 16; off; off >>= 1)
            ssum += __shfl_xor_sync(0xffffffffu, ssum, off);
        float c = e / ssum;

#pragma unroll
        for (int d = 0; d < D_; d++) sreg[d] = fmaf(c, u[d], sreg[d]);
    }

    // per-warp partial -> smem, transposed [d*32 + o]: conflict-free
#pragma unroll
    for (int d = 0; d < D_; d++) sacc[w][d * O_ + lane] = sreg[d];
    __syncthreads();

    // block reduce 8 warps, one atomicAdd per element
    for (int idx = threadIdx.x; idx < OD_; idx += 256) {
        float a = 0.f;
#pragma unroll
        for (int ww = 0; ww < 8; ww++) a += sacc[ww][idx];
        atomicAdd(&sout[b * OD_ + idx], a);
    }
}

// ---------------- launch ----------------------------------------------------
extern "C" void kernel_launch(void* const* d_in, const int* in_sizes, int n_in,
                              void* d_out, int out_size) {
    const float* x  = (const float*)d_in[0];
    const float* Wg = (const float*)d_in[1];
    if (n_in >= 2 && in_sizes[0] > in_sizes[1]) {   // be robust to input order
        x  = (const float*)d_in[1];
        Wg = (const float*)d_in[0];
    }
    float* out = (float*)d_out;

    k_zero  <<<64, 1024>>>();
    k_uhat  <<<P_, 256>>>(x, Wg);
    k_s0    <<<dim3(16, B_), 256>>>();
    k_squash<<<B_, 1024>>>(1, 1.f / 32.f, nullptr);   // v1 = squash(mean_o-weighted s)
    k_route <<<dim3(32, B_), 256>>>(1);               // b1, s2
    k_squash<<<B_, 1024>>>(2, 1.f, nullptr);          // v2
    k_route <<<dim3(32, B_), 256>>>(2);               // b2, s3
    k_squash<<<B_, 1024>>>(3, 1.f, out);              // final output
}

// round 4
// speedup vs baseline: 1.7109x; 1.7109x over previous
#include <cuda_runtime.h>
#include <cuda_fp16.h>
#include <cstddef>
#include <cstdint>

// Shapes: B=64, C=32, H=8, Wd=8 -> P=2048 positions, I=16, O=32, D=32
#define B_  64
#define P_  2048
#define I_  16
#define O_  32
#define D_  32
#define OD_ 1024                 // O_*D_
#define EPS 1e-6f

// ---------------- scratch (device globals; no allocation allowed) ----------
__device__ __half g_uhat[(size_t)B_ * P_ * OD_];  // 256 MB  [b][p][o][d] fp16
__device__ float  g_b[(size_t)B_ * P_ * O_];      // 16 MB   [b][p][o]
__device__ float  g_s1[B_ * OD_];                 // transposed [b][d*32+o]
__device__ float  g_s2[B_ * OD_];
__device__ float  g_s3[B_ * OD_];

// ---------------- packed fp32x2 helpers (sm_100+ PTX) -----------------------
__device__ __forceinline__ unsigned long long pk2(float lo, float hi) {
    unsigned long long r;
    asm("mov.b64 %0, {%1, %2};" : "=l"(r) : "f"(lo), "f"(hi));
    return r;
}
__device__ __forceinline__ unsigned long long fma2(unsigned long long a,
                                                   unsigned long long b,
                                                   unsigned long long c) {
    unsigned long long d;
    asm("fma.rn.f32x2 %0, %1, %2, %3;" : "=l"(d) : "l"(a), "l"(b), "l"(c));
    return d;
}
__device__ __forceinline__ float2 upk2(unsigned long long v) {
    float2 r;
    asm("mov.b64 {%0, %1}, %2;" : "=f"(r.x), "=f"(r.y) : "l"(v));
    return r;
}

// ---------------- zero the atomic accumulators every launch -----------------
__global__ void k_zero() {
    int i = blockIdx.x * blockDim.x + threadIdx.x;
    if (i < B_ * OD_) { g_s1[i] = 0.f; g_s2[i] = 0.f; g_s3[i] = 0.f; }
}

// ---------------- K1: u_hat[b,p,o,d] = sum_i x[b,p,i] * W[p,o,i,d] ---------
// One block per p. Thread t owns (o = t>>3, d0 = (t&7)*4), i.e. od = 4t.
// W slice in registers as packed f32x2 pairs; x broadcast from smem as
// pre-duplicated (xv, xv) 64-bit words; inner product via fma.rn.f32x2.
__global__ void __launch_bounds__(256) k_uhat(const float* __restrict__ x,
                                              const float* __restrict__ Wg) {
    const int p  = blockIdx.x;
    const int t  = threadIdx.x;
    const int o  = t >> 3;
    const int d0 = (t & 7) * 4;

    __shared__ unsigned long long sx2[B_ * I_];   // 8 KB: (xv,xv) per (b,i)
    for (int k = t; k < B_ * I_; k += 256) {
        int b = k >> 4, i = k & 15;
        float xv = x[(size_t)b * (P_ * I_) + (size_t)p * I_ + i];
        sx2[k] = pk2(xv, xv);
    }

    // W[p, o, i, d0..d0+3] -> two packed pairs per i
    unsigned long long w01[I_], w23[I_];
    const float4* wp = reinterpret_cast<const float4*>(
        Wg + (size_t)p * (O_ * I_ * D_) + (size_t)o * (I_ * D_) + d0);
#pragma unroll
    for (int i = 0; i < I_; i++) {
        float4 wv = wp[i * (D_ / 4)];
        w01[i] = pk2(wv.x, wv.y);
        w23[i] = pk2(wv.z, wv.w);
    }

    __syncthreads();

    __half* up = g_uhat + (size_t)p * OD_ + t * 4;
    const size_t bstride = (size_t)P_ * OD_;
#pragma unroll 2
    for (int b = 0; b < B_; b++) {
        const unsigned long long* xb = sx2 + b * I_;
        unsigned long long a01 = 0ull, a23 = 0ull;   // (0.f, 0.f)
#pragma unroll
        for (int i = 0; i < I_; i++) {
            unsigned long long xx = xb[i];
            a01 = fma2(xx, w01[i], a01);
            a23 = fma2(xx, w23[i], a23);
        }
        float2 f01 = upk2(a01), f23 = upk2(a23);
        __half2 h01 = __floats2half2_rn(f01.x, f01.y);
        __half2 h23 = __floats2half2_rn(f23.x, f23.y);
        uint2 st;
        st.x = *reinterpret_cast<unsigned*>(&h01);
        st.y = *reinterpret_cast<unsigned*>(&h23);
        *reinterpret_cast<uint2*>(up + (size_t)b * bstride) = st;
    }
}

// ---------------- s1 = sum_p u_hat  (uniform c applied as 1/32 later) ------
// grid (16 p-slices, 64 b), 256 threads; thread t owns od = 4t..4t+3.
__global__ void __launch_bounds__(256) k_s0() {
    const int b     = blockIdx.y;
    const int pbase = blockIdx.x * 128;
    const int t     = threadIdx.x;

    const uint2* up = reinterpret_cast<const uint2*>(
        g_uhat + ((size_t)b * P_ + pbase) * OD_ + t * 4);
    float4 a = make_float4(0.f, 0.f, 0.f, 0.f);
    for (int p = 0; p < 128; p++) {
        uint2 v = up[(size_t)p * (OD_ / 4)];
        float2 f0 = __half22float2(*reinterpret_cast<__half2*>(&v.x));
        float2 f1 = __half22float2(*reinterpret_cast<__half2*>(&v.y));
        a.x += f0.x; a.y += f0.y; a.z += f1.x; a.w += f1.y;
    }
    const int o = t >> 3, d0 = (t & 7) * 4;
    float* s = g_s1 + b * OD_;
    atomicAdd(&s[(d0 + 0) * O_ + o], a.x);
    atomicAdd(&s[(d0 + 1) * O_ + o], a.y);
    atomicAdd(&s[(d0 + 2) * O_ + o], a.z);
    atomicAdd(&s[(d0 + 3) * O_ + o], a.w);
}

// ---------------- fused routing pass (squash folded into prologue) ----------
// Prologue: lane=o reads its (b, :, o) column of s (transposed layout,
// coalesced), computes v = squash(s*scale) entirely in registers, no shuffles.
// Main: ONE read of u_hat does b_new = b_prev + u.v ; c = softmax_o(b_new);
// s_next += c*u (per-warp register partials -> smem -> atomics).
// grid (32 p-chunks of 64, 64 b), 256 threads = 8 warps, 8 p's per warp.
__global__ void __launch_bounds__(256) k_route(int pass) {
    const int b     = blockIdx.y;
    const int pbase = blockIdx.x * 64;
    const int w     = threadIdx.x >> 5;
    const int lane  = threadIdx.x & 31;

    const float* sin   = (pass == 1) ? g_s1 : g_s2;
    const float  scale = (pass == 1) ? (1.f / 32.f) : 1.f;
    float*       sout  = (pass == 1) ? g_s2 : g_s3;

    __shared__ float sacc[8][OD_];     // 32 KB per-warp partials (transposed)

    // v = squash(s*scale) for this lane's o
    float v[D_];
    float sq = 0.f;
#pragma unroll
    for (int d = 0; d < D_; d++) {
        float sv = sin[b * OD_ + d * O_ + lane] * scale;
        v[d] = sv;
        sq = fmaf(sv, sv, sq);
    }
    float f = sq / ((1.f + sq) * (sqrtf(sq) + EPS));
#pragma unroll
    for (int d = 0; d < D_; d++) v[d] *= f;

    float sreg[D_];
#pragma unroll
    for (int d = 0; d < D_; d++) sreg[d] = 0.f;

    for (int j = 0; j < 8; j++) {
        const int p = pbase + w * 8 + j;
        const uint4* up = reinterpret_cast<const uint4*>(
            g_uhat + ((size_t)b * P_ + p) * OD_ + lane * D_);
        float u[D_];
#pragma unroll
        for (int q = 0; q < 4; q++) {
            uint4 t4 = up[q];
            float2 f0 = __half22float2(*reinterpret_cast<__half2*>(&t4.x));
            float2 f1 = __half22float2(*reinterpret_cast<__half2*>(&t4.y));
            float2 f2 = __half22float2(*reinterpret_cast<__half2*>(&t4.z));
            float2 f3 = __half22float2(*reinterpret_cast<__half2*>(&t4.w));
            u[q * 8 + 0] = f0.x; u[q * 8 + 1] = f0.y;
            u[q * 8 + 2] = f1.x; u[q * 8 + 3] = f1.y;
            u[q * 8 + 4] = f2.x; u[q * 8 + 5] = f2.y;
            u[q * 8 + 6] = f3.x; u[q * 8 + 7] = f3.y;
        }
        float dot = 0.f;
#pragma unroll
        for (int d = 0; d < D_; d++) dot = fmaf(u[d], v[d], dot);

        const size_t bidx = ((size_t)b * P_ + p) * O_ + lane;
        float bn = dot;
        if (pass == 2) bn += g_b[bidx];
        else           g_b[bidx] = bn;   // only pass 1 needs b stored

        // softmax over o (= warp lanes), max-subtracted
        float m = bn;
#pragma unroll
        for (int off = 16; off; off >>= 1)
            m = fmaxf(m, __shfl_xor_sync(0xffffffffu, m, off));
        float e = __expf(bn - m);
        float ssum = e;
#pragma unroll
        for (int off = 16; off; off >>= 1)
            ssum += __shfl_xor_sync(0xffffffffu, ssum, off);
        float c = e / ssum;

#pragma unroll
        for (int d = 0; d < D_; d++) sreg[d] = fmaf(c, u[d], sreg[d]);
    }

    // per-warp partial -> smem, transposed [d*32 + o]: conflict-free
#pragma unroll
    for (int d = 0; d < D_; d++) sacc[w][d * O_ + lane] = sreg[d];
    __syncthreads();

    for (int idx = threadIdx.x; idx < OD_; idx += 256) {
        float a = 0.f;
#pragma unroll
        for (int ww = 0; ww < 8; ww++) a += sacc[ww][idx];
        atomicAdd(&sout[b * OD_ + idx], a);
    }
}

// ---------------- final squash -> output (b, o, d) layout -------------------
// grid 64 (b), 256 threads = 8 warps; lane = o, warp handles 4 d per pass.
__global__ void k_out(float* __restrict__ out) {
    const int b    = blockIdx.x;
    const int lane = threadIdx.x & 31;   // o
    const int w    = threadIdx.x >> 5;
    // every warp redundantly computes its lane's full column (cheap, L2-hot)
    float s[D_], sq = 0.f;
#pragma unroll
    for (int d = 0; d < D_; d++) {
        float sv = g_s3[b * OD_ + d * O_ + lane];
        s[d] = sv;
        sq = fmaf(sv, sv, sq);
    }
    float f = sq / ((1.f + sq) * (sqrtf(sq) + EPS));
    // warp w writes d = w*4 .. w*4+3
#pragma unroll
    for (int k = 0; k < 4; k++) {
        int d = w * 4 + k;
        out[b * OD_ + lane * D_ + d] = s[d] * f;
    }
}

// ---------------- launch ----------------------------------------------------
extern "C" void kernel_launch(void* const* d_in, const int* in_sizes, int n_in,
                              void* d_out, int out_size) {
    const float* x  = (const float*)d_in[0];
    const float* Wg = (const float*)d_in[1];
    if (n_in >= 2 && in_sizes[0] > in_sizes[1]) {   // robust to input order
        x  = (const float*)d_in[1];
        Wg = (const float*)d_in[0];
    }
    float* out = (float*)d_out;

    k_zero <<<64, 1024>>>();
    k_uhat <<<P_, 256>>>(x, Wg);
    k_s0   <<<dim3(16, B_), 256>>>();
    k_route<<<dim3(32, B_), 256>>>(1);   // v1 inline, writes b1, accumulates s2
    k_route<<<dim3(32, B_), 256>>>(2);   // v2 inline, reads b1, accumulates s3
    k_out  <<<64, 256>>>(out);           // v3 = squash(s3)
}